// round 1
// baseline (speedup 1.0000x reference)
#include <cuda_runtime.h>
#include <math.h>

#define DM 1024
#define NH 16
#define DH 64
#define SQ 2048
#define NB 2
#define MR (NB*SQ)   // 4096 rows

// Scratch (allocation-free rule: __device__ globals)
__device__ float g_q[(size_t)NB*NH*SQ*DH];
__device__ float g_k[(size_t)NB*NH*SQ*DH];
__device__ float g_v[(size_t)NB*NH*SQ*DH];
__device__ float g_ctx[(size_t)MR*DM];

// ---------------------------------------------------------------------------
// SGEMM: C[M=4096, N=1024] = A[4096,1024] @ W[1024,1024] + bias
// 128x128 block tile, BK=8, 256 threads, 8x8 per-thread microtile.
// mode 0: QKV (blockIdx.z selects W/bias; scatter into [B,H,S,Dh] layout)
// mode 1: plain row-major store to Cout
// ---------------------------------------------------------------------------
__global__ __launch_bounds__(256)
void sgemm_k(const float* __restrict__ A_in,
             const float* __restrict__ W0, const float* __restrict__ W1,
             const float* __restrict__ W2,
             const float* __restrict__ b0, const float* __restrict__ b1,
             const float* __restrict__ b2,
             float* __restrict__ Cout, int mode)
{
    const float* A = A_in ? A_in : g_ctx;
    int z = blockIdx.z;
    const float* W;
    const float* bias;
    if (mode == 0) {
        W    = (z == 0) ? W0 : (z == 1) ? W1 : W2;
        bias = (z == 0) ? b0 : (z == 1) ? b1 : b2;
    } else {
        W = W0; bias = b0;
    }

    __shared__ float As[8][128];   // transposed A tile: As[k][m]
    __shared__ float Bs[8][128];   // Bs[k][n]

    int tid  = threadIdx.x;
    int aRow = tid >> 1;           // 0..127
    int aCol = (tid & 1) << 2;     // 0 or 4
    int bRow = tid >> 5;           // 0..7
    int bCol = (tid & 31) << 2;    // 0..124
    int tRow = (tid >> 4) << 3;    // 0..120 step 8
    int tCol = (tid & 15) << 3;    // 0..120 step 8

    const float* Ap = A + (size_t)(blockIdx.y * 128 + aRow) * DM + aCol;
    const float* Bp = W + (size_t)bRow * DM + blockIdx.x * 128 + bCol;

    float acc[8][8];
#pragma unroll
    for (int i = 0; i < 8; i++)
#pragma unroll
        for (int j = 0; j < 8; j++) acc[i][j] = 0.f;

    for (int k0 = 0; k0 < DM; k0 += 8) {
        float4 a4 = *(const float4*)(Ap + k0);
        As[aCol + 0][aRow] = a4.x;
        As[aCol + 1][aRow] = a4.y;
        As[aCol + 2][aRow] = a4.z;
        As[aCol + 3][aRow] = a4.w;
        *(float4*)(&Bs[bRow][bCol]) = *(const float4*)(Bp + (size_t)k0 * DM);
        __syncthreads();
#pragma unroll
        for (int kk = 0; kk < 8; kk++) {
            float rM[8], rN[8];
            *(float4*)&rM[0] = *(const float4*)&As[kk][tRow];
            *(float4*)&rM[4] = *(const float4*)&As[kk][tRow + 4];
            *(float4*)&rN[0] = *(const float4*)&Bs[kk][tCol];
            *(float4*)&rN[4] = *(const float4*)&Bs[kk][tCol + 4];
#pragma unroll
            for (int i = 0; i < 8; i++)
#pragma unroll
                for (int j = 0; j < 8; j++)
                    acc[i][j] = fmaf(rM[i], rN[j], acc[i][j]);
        }
        __syncthreads();
    }

    int nb = blockIdx.x * 128 + tCol;
    float bl[8];
#pragma unroll
    for (int j = 0; j < 8; j++) bl[j] = bias[nb + j];

    if (mode == 1) {
#pragma unroll
        for (int i = 0; i < 8; i++) {
            int m = blockIdx.y * 128 + tRow + i;
            float4 o0 = make_float4(acc[i][0] + bl[0], acc[i][1] + bl[1],
                                    acc[i][2] + bl[2], acc[i][3] + bl[3]);
            float4 o1 = make_float4(acc[i][4] + bl[4], acc[i][5] + bl[5],
                                    acc[i][6] + bl[6], acc[i][7] + bl[7]);
            *(float4*)&Cout[(size_t)m * DM + nb]     = o0;
            *(float4*)&Cout[(size_t)m * DM + nb + 4] = o1;
        }
    } else {
        float* out = (z == 0) ? g_q : (z == 1) ? g_k : g_v;
        int h = nb >> 6;        // head (8 cols stay inside one head: 8 | 64)
        int d = nb & 63;
#pragma unroll
        for (int i = 0; i < 8; i++) {
            int m = blockIdx.y * 128 + tRow + i;
            int b = m >> 11;    // / SQ
            int s = m & 2047;
            size_t idx = ((size_t)((b * NH + h) * SQ + s)) * DH + d;
            float4 o0 = make_float4(acc[i][0] + bl[0], acc[i][1] + bl[1],
                                    acc[i][2] + bl[2], acc[i][3] + bl[3]);
            float4 o1 = make_float4(acc[i][4] + bl[4], acc[i][5] + bl[5],
                                    acc[i][6] + bl[6], acc[i][7] + bl[7]);
            *(float4*)&out[idx]     = o0;
            *(float4*)&out[idx + 4] = o1;
        }
    }
}

// ---------------------------------------------------------------------------
// Causal flash attention, 64x64 tiles, fp32.
// grid: (SQ/64, NB*NH), 256 threads (16x16), 4x4 microtiles.
// Exact reference semantics: mask fill -1e9 BEFORE scaling by 1/8.
// ---------------------------------------------------------------------------
__global__ __launch_bounds__(256)
void attn_k()
{
    __shared__ float Qs[64 * 64];     // Q[i][d], plain (reads are broadcast)
    __shared__ float KPs[64 * 64];    // K (xor-rotated rows), reused as P
    __shared__ float Vs[64 * 64];     // V[j][d], plain

    int tid = threadIdx.x;
    int tx = tid & 15, ty = tid >> 4;
    int qt = blockIdx.x;
    int bh = blockIdx.y;

    const float* Qg = g_q + (size_t)bh * SQ * DH + (size_t)qt * 64 * DH;
    const float* Kg = g_k + (size_t)bh * SQ * DH;
    const float* Vg = g_v + (size_t)bh * SQ * DH;

#pragma unroll
    for (int t = 0; t < 4; t++) {
        int idx = t * 1024 + tid * 4;
        *(float4*)&Qs[idx] = *(const float4*)&Qg[idx];
    }

    float m_i[4], l_i[4], acc[4][4];
#pragma unroll
    for (int ii = 0; ii < 4; ii++) {
        m_i[ii] = -INFINITY;
        l_i[ii] = 0.f;
#pragma unroll
        for (int dd = 0; dd < 4; dd++) acc[ii][dd] = 0.f;
    }

    for (int kt = 0; kt <= qt; kt++) {
        __syncthreads();   // protect KPs/Vs from previous iteration readers
        const float* Kt = Kg + (size_t)kt * 64 * DH;
        const float* Vt = Vg + (size_t)kt * 64 * DH;
#pragma unroll
        for (int t = 0; t < 16; t++) {
            int idx = t * 256 + tid;
            int j = idx >> 6, d = idx & 63;
            KPs[j * 64 + ((d + j) & 63)] = Kt[idx];   // rotate to avoid 16-way LDS conflicts
        }
#pragma unroll
        for (int t = 0; t < 4; t++) {
            int idx = t * 1024 + tid * 4;
            *(float4*)&Vs[idx] = *(const float4*)&Vt[idx];
        }
        __syncthreads();

        // S = Q K^T (this thread: rows ty*4.., cols tx*4..)
        float s[4][4];
#pragma unroll
        for (int ii = 0; ii < 4; ii++)
#pragma unroll
            for (int jj = 0; jj < 4; jj++) s[ii][jj] = 0.f;

#pragma unroll 4
        for (int d = 0; d < 64; d++) {
            float qv[4], kv[4];
#pragma unroll
            for (int ii = 0; ii < 4; ii++) qv[ii] = Qs[(ty * 4 + ii) * 64 + d];
#pragma unroll
            for (int jj = 0; jj < 4; jj++) {
                int j = tx * 4 + jj;
                kv[jj] = KPs[j * 64 + ((d + j) & 63)];
            }
#pragma unroll
            for (int ii = 0; ii < 4; ii++)
#pragma unroll
                for (int jj = 0; jj < 4; jj++)
                    s[ii][jj] = fmaf(qv[ii], kv[jj], s[ii][jj]);
        }

        // mask (before-scale semantics: -1e9/8 = -1.25e8) + scale
        bool diag = (kt == qt);
#pragma unroll
        for (int ii = 0; ii < 4; ii++) {
            int qi = qt * 64 + ty * 4 + ii;
#pragma unroll
            for (int jj = 0; jj < 4; jj++) {
                int kj = kt * 64 + tx * 4 + jj;
                float v = s[ii][jj] * 0.125f;
                if (diag && kj > qi) v = -1.25e8f;
                s[ii][jj] = v;
            }
        }

        // online softmax update; row reduce across 16 tx lanes (low 4 lane bits)
        float p[4][4];
#pragma unroll
        for (int ii = 0; ii < 4; ii++) {
            float rm = fmaxf(fmaxf(s[ii][0], s[ii][1]), fmaxf(s[ii][2], s[ii][3]));
            rm = fmaxf(rm, __shfl_xor_sync(0xffffffffu, rm, 1));
            rm = fmaxf(rm, __shfl_xor_sync(0xffffffffu, rm, 2));
            rm = fmaxf(rm, __shfl_xor_sync(0xffffffffu, rm, 4));
            rm = fmaxf(rm, __shfl_xor_sync(0xffffffffu, rm, 8));
            float mnew = fmaxf(m_i[ii], rm);
            float corr = __expf(m_i[ii] - mnew);   // first iter: exp(-inf)=0
            float rs = 0.f;
#pragma unroll
            for (int jj = 0; jj < 4; jj++) {
                float pv = __expf(s[ii][jj] - mnew);
                p[ii][jj] = pv;
                rs += pv;
            }
            rs += __shfl_xor_sync(0xffffffffu, rs, 1);
            rs += __shfl_xor_sync(0xffffffffu, rs, 2);
            rs += __shfl_xor_sync(0xffffffffu, rs, 4);
            rs += __shfl_xor_sync(0xffffffffu, rs, 8);
            l_i[ii] = l_i[ii] * corr + rs;
            m_i[ii] = mnew;
#pragma unroll
            for (int dd = 0; dd < 4; dd++) acc[ii][dd] *= corr;
        }

        __syncthreads();   // everyone done reading K tile
#pragma unroll
        for (int ii = 0; ii < 4; ii++)
#pragma unroll
            for (int jj = 0; jj < 4; jj++)
                KPs[(ty * 4 + ii) * 64 + tx * 4 + jj] = p[ii][jj];
        __syncthreads();

        // acc += P @ V (this thread: rows ty*4.., d-cols tx*4..)
#pragma unroll 2
        for (int j = 0; j < 64; j++) {
            float4 v4 = *(const float4*)&Vs[j * 64 + tx * 4];
#pragma unroll
            for (int ii = 0; ii < 4; ii++) {
                float pv = KPs[(ty * 4 + ii) * 64 + j];
                acc[ii][0] = fmaf(pv, v4.x, acc[ii][0]);
                acc[ii][1] = fmaf(pv, v4.y, acc[ii][1]);
                acc[ii][2] = fmaf(pv, v4.z, acc[ii][2]);
                acc[ii][3] = fmaf(pv, v4.w, acc[ii][3]);
            }
        }
    }

    // finalize: ctx in [B, S, D_MODEL] layout for the output GEMM
    int b = bh >> 4, h = bh & 15;
#pragma unroll
    for (int ii = 0; ii < 4; ii++) {
        float inv = 1.0f / l_i[ii];
        int row = b * SQ + qt * 64 + ty * 4 + ii;
        float4 o = make_float4(acc[ii][0] * inv, acc[ii][1] * inv,
                               acc[ii][2] * inv, acc[ii][3] * inv);
        *(float4*)&g_ctx[(size_t)row * DM + h * DH + tx * 4] = o;
    }
}

extern "C" void kernel_launch(void* const* d_in, const int* in_sizes, int n_in,
                              void* d_out, int out_size)
{
    const float* x  = (const float*)d_in[0];
    const float* Wq = (const float*)d_in[1];
    const float* bq = (const float*)d_in[2];
    const float* Wk = (const float*)d_in[3];
    const float* bk = (const float*)d_in[4];
    const float* Wv = (const float*)d_in[5];
    const float* bv = (const float*)d_in[6];
    const float* Wo = (const float*)d_in[7];
    const float* bo = (const float*)d_in[8];
    float* out = (float*)d_out;

    // QKV projections (z selects weight; writes g_q/g_k/g_v in [B,H,S,Dh])
    sgemm_k<<<dim3(DM / 128, MR / 128, 3), 256>>>(x, Wq, Wk, Wv, bq, bk, bv,
                                                  nullptr, 0);
    // causal attention -> g_ctx [B,S,D_MODEL]
    attn_k<<<dim3(SQ / 64, NB * NH), 256>>>();
    // output projection -> d_out
    sgemm_k<<<dim3(DM / 128, MR / 128, 1), 256>>>(nullptr, Wo, Wo, Wo,
                                                  bo, bo, bo, out, 1);
}

// round 16
// speedup vs baseline: 1.5069x; 1.5069x over previous
#include <cuda_runtime.h>
#include <cuda_bf16.h>
#include <math.h>
#include <stdint.h>

#define DM 1024
#define NH 16
#define DH 64
#define SQ 2048
#define NB 2
#define MR (NB*SQ)   // 4096

#define KC 64              // bf16 K elements per chunk (rows of 128B)
#define NCHUNK 16          // 1024/64
#define TILE_B 16384       // 128 rows * 128B
#define STAGE_B (4*TILE_B) // Ah,Al,Bh,Bl
#define SMEM_DYN (2*STAGE_B + 1024)

// ---------------- scratch (__device__ globals; allocation-free rule) --------
__device__ float g_q[(size_t)NB*NH*SQ*DH];
__device__ float g_k[(size_t)NB*NH*SQ*DH];
__device__ float g_v[(size_t)NB*NH*SQ*DH];
__device__ __nv_bfloat16 g_xh[(size_t)MR*DM], g_xl[(size_t)MR*DM];
__device__ __nv_bfloat16 g_wh[4][(size_t)DM*DM], g_wl[4][(size_t)DM*DM]; // [n][k]
__device__ __nv_bfloat16 g_ch[(size_t)MR*DM], g_cl[(size_t)MR*DM];       // ctx hi/lo

// ---------------- helpers ---------------------------------------------------
__device__ __forceinline__ uint32_t sm_u32(const void* p) {
    uint32_t a;
    asm("{ .reg .u64 t; cvta.to.shared.u64 t, %1; cvt.u32.u64 %0, t; }"
        : "=r"(a) : "l"(p));
    return a;
}
__device__ __forceinline__ void ldsm4(uint32_t* r, uint32_t addr) {
    asm volatile("ldmatrix.sync.aligned.m8n8.x4.shared.b16 {%0,%1,%2,%3}, [%4];"
                 : "=r"(r[0]), "=r"(r[1]), "=r"(r[2]), "=r"(r[3]) : "r"(addr));
}
__device__ __forceinline__ void mma16816(float* c, const uint32_t* a, const uint32_t* b) {
    asm volatile("mma.sync.aligned.m16n8k16.row.col.f32.bf16.bf16.f32 "
                 "{%0,%1,%2,%3}, {%4,%5,%6,%7}, {%8,%9}, {%0,%1,%2,%3};"
                 : "+f"(c[0]), "+f"(c[1]), "+f"(c[2]), "+f"(c[3])
                 : "r"(a[0]), "r"(a[1]), "r"(a[2]), "r"(a[3]),
                   "r"(b[0]), "r"(b[1]));
}
#define CP_COMMIT() asm volatile("cp.async.commit_group;" ::: "memory")

// ---------------- conversion kernels ---------------------------------------
__global__ void convx_k(const float* __restrict__ x) {
    int i = blockIdx.x * 256 + threadIdx.x;        // over MR*DM/4 float4s
    float4 v = ((const float4*)x)[i];
    float vv[4] = {v.x, v.y, v.z, v.w};
    union { __nv_bfloat16 h[4]; uint2 u; } ph, pl;
#pragma unroll
    for (int q = 0; q < 4; q++) {
        __nv_bfloat16 h = __float2bfloat16(vv[q]);
        ph.h[q] = h;
        pl.h[q] = __float2bfloat16(vv[q] - __bfloat162float(h));
    }
    ((uint2*)g_xh)[i] = ph.u;
    ((uint2*)g_xl)[i] = pl.u;
}

__global__ void convw_k(const float* __restrict__ W0, const float* __restrict__ W1,
                        const float* __restrict__ W2, const float* __restrict__ W3) {
    __shared__ float t[32][33];
    int z = blockIdx.z;
    const float* W = (z == 0) ? W0 : (z == 1) ? W1 : (z == 2) ? W2 : W3;
    int n0 = blockIdx.x * 32, k0 = blockIdx.y * 32;
    for (int j = threadIdx.y; j < 32; j += 8)
        t[j][threadIdx.x] = W[(size_t)(k0 + j) * DM + n0 + threadIdx.x];
    __syncthreads();
    for (int j = threadIdx.y; j < 32; j += 8) {
        float v = t[threadIdx.x][j];               // = W[k0+tx][n0+j]
        __nv_bfloat16 h = __float2bfloat16(v);
        __nv_bfloat16 l = __float2bfloat16(v - __bfloat162float(h));
        size_t o = (size_t)(n0 + j) * DM + k0 + threadIdx.x;
        g_wh[z][o] = h;
        g_wl[z][o] = l;
    }
}

// ---------------- mma.sync split-bf16 GEMM ---------------------------------
// C[128x128] = A[128x1024] @ B[128x1024]^T  (B stored [n][k] K-major)
// Tile load: 128 rows x 64 bf16 (128B rows), XOR-swizzled 16B chunks.
__device__ __forceinline__ void load_tile(uint32_t sdst,
                                          const __nv_bfloat16* __restrict__ g,
                                          int tid) {
#pragma unroll
    for (int i = 0; i < 4; i++) {
        int lin = i * 256 + tid;              // 1024 chunks of 16B
        int row = lin >> 3, cc = lin & 7;
        uint32_t dst = sdst + row * 128 + ((cc ^ (row & 7)) << 4);
        const __nv_bfloat16* src = g + (size_t)row * DM + cc * 8;
        asm volatile("cp.async.cg.shared.global [%0], [%1], 16;"
                     :: "r"(dst), "l"(src) : "memory");
    }
}

__device__ __forceinline__ uint32_t sw_addr(uint32_t base, int row, int cc) {
    return base + row * 128 + ((cc ^ (row & 7)) << 4);
}

__global__ __launch_bounds__(256)
void gemm_tc(const float* __restrict__ b0, const float* __restrict__ b1,
             const float* __restrict__ b2, float* __restrict__ Cout, int mode)
{
    extern __shared__ __align__(1024) char dsm[];

    const int tid = threadIdx.x;
    const int wid = tid >> 5;
    const int lane = tid & 31;
    const int wm = wid >> 1;          // 0..3  (rows)
    const int wn = wid & 1;           // 0..1  (cols)
    const int bx = blockIdx.x, by = blockIdx.y, z = blockIdx.z;
    const int widx = (mode == 0) ? z : 3;

    const __nv_bfloat16* Ah = ((mode == 0) ? g_xh : g_ch) + (size_t)(by * 128) * DM;
    const __nv_bfloat16* Al = ((mode == 0) ? g_xl : g_cl) + (size_t)(by * 128) * DM;
    const __nv_bfloat16* Bh = g_wh[widx] + (size_t)(bx * 128) * DM;
    const __nv_bfloat16* Bl = g_wl[widx] + (size_t)(bx * 128) * DM;
    const float* bias = (mode == 1) ? b0 : ((z == 0) ? b0 : (z == 1) ? b1 : b2);

    uint32_t sb = (sm_u32(dsm) + 1023u) & ~1023u;

    float acc[2][8][4];
#pragma unroll
    for (int mt = 0; mt < 2; mt++)
#pragma unroll
        for (int nt = 0; nt < 8; nt++)
#pragma unroll
            for (int q = 0; q < 4; q++) acc[mt][nt][q] = 0.f;

    // ldmatrix per-lane row/chunk indices
    const int aRowL = wm * 32 + (lane & 15);            // + mt*16
    const int aCCh  = lane >> 4;                         // + ks*2
    const int bRowL = wn * 64 + (lane & 7) + ((lane & 16) >> 1);  // + p*16
    const int bCCh  = (lane >> 3) & 1;                   // + ks*2

    // preload chunk 0 -> stage 0
    {
        uint32_t s0 = sb;
        load_tile(s0,              Ah, tid);
        load_tile(s0 + TILE_B,     Al, tid);
        load_tile(s0 + 2*TILE_B,   Bh, tid);
        load_tile(s0 + 3*TILE_B,   Bl, tid);
        CP_COMMIT();
    }

    for (int c = 0; c < NCHUNK; c++) {
        if (c + 1 < NCHUNK) {
            uint32_t sN = sb + ((c + 1) & 1) * STAGE_B;
            load_tile(sN,              Ah + (c + 1) * KC, tid);
            load_tile(sN + TILE_B,     Al + (c + 1) * KC, tid);
            load_tile(sN + 2*TILE_B,   Bh + (c + 1) * KC, tid);
            load_tile(sN + 3*TILE_B,   Bl + (c + 1) * KC, tid);
            CP_COMMIT();
            asm volatile("cp.async.wait_group 1;" ::: "memory");
        } else {
            asm volatile("cp.async.wait_group 0;" ::: "memory");
        }
        __syncthreads();

        uint32_t sC = sb + (c & 1) * STAGE_B;
        uint32_t sAh = sC, sAl = sC + TILE_B, sBh = sC + 2*TILE_B, sBl = sC + 3*TILE_B;

#pragma unroll
        for (int ks = 0; ks < 4; ks++) {
            uint32_t ah[2][4], al[2][4], bhf[4][4], blf[4][4];
#pragma unroll
            for (int mt = 0; mt < 2; mt++) {
                int r = aRowL + mt * 16, cc = ks * 2 + aCCh;
                ldsm4(ah[mt], sw_addr(sAh, r, cc));
                ldsm4(al[mt], sw_addr(sAl, r, cc));
            }
#pragma unroll
            for (int p = 0; p < 4; p++) {
                int r = bRowL + p * 16, cc = ks * 2 + bCCh;
                ldsm4(bhf[p], sw_addr(sBh, r, cc));
                ldsm4(blf[p], sw_addr(sBl, r, cc));
            }
#pragma unroll
            for (int mt = 0; mt < 2; mt++)
#pragma unroll
                for (int p = 0; p < 4; p++) {
                    mma16816(acc[mt][2*p],   ah[mt], &bhf[p][0]);
                    mma16816(acc[mt][2*p],   ah[mt], &blf[p][0]);
                    mma16816(acc[mt][2*p],   al[mt], &bhf[p][0]);
                    mma16816(acc[mt][2*p+1], ah[mt], &bhf[p][2]);
                    mma16816(acc[mt][2*p+1], ah[mt], &blf[p][2]);
                    mma16816(acc[mt][2*p+1], al[mt], &bhf[p][2]);
                }
        }
        __syncthreads();
    }

    // epilogue: regs -> global (+bias); float2 per store
    const int rL = lane >> 2;            // 0..7
    const int cL = (lane & 3) * 2;       // 0,2,4,6
#pragma unroll
    for (int mt = 0; mt < 2; mt++) {
#pragma unroll
        for (int nt = 0; nt < 8; nt++) {
            int n = bx * 128 + wn * 64 + nt * 8 + cL;
            float bz0 = bias[n], bz1 = bias[n + 1];
            int m0 = by * 128 + wm * 32 + mt * 16 + rL;
            float2 v0 = make_float2(acc[mt][nt][0] + bz0, acc[mt][nt][1] + bz1);
            float2 v1 = make_float2(acc[mt][nt][2] + bz0, acc[mt][nt][3] + bz1);
            if (mode == 1) {
                *(float2*)&Cout[(size_t)m0 * DM + n]       = v0;
                *(float2*)&Cout[(size_t)(m0 + 8) * DM + n] = v1;
            } else {
                float* outp = (z == 0) ? g_q : (z == 1) ? g_k : g_v;
                int hh = n >> 6, d = n & 63;
                int b = m0 >> 11, s0 = m0 & 2047;
                *(float2*)&outp[((size_t)((b * NH + hh) * SQ + s0)) * DH + d] = v0;
                int m1 = m0 + 8, b1_ = m1 >> 11, s1 = m1 & 2047;
                *(float2*)&outp[((size_t)((b1_ * NH + hh) * SQ + s1)) * DH + d] = v1;
            }
        }
    }
}

// ---------------- causal flash attention (fp32 SIMT, proven core) ----------
__global__ __launch_bounds__(256)
void attn_k()
{
    __shared__ float Qs[64 * 64];
    __shared__ float KPs[64 * 64];
    __shared__ float Vs[64 * 64];

    int tid = threadIdx.x;
    int tx = tid & 15, ty = tid >> 4;
    int qt = blockIdx.x;
    int bh = blockIdx.y;

    const float* Qg = g_q + (size_t)bh * SQ * DH + (size_t)qt * 64 * DH;
    const float* Kg = g_k + (size_t)bh * SQ * DH;
    const float* Vg = g_v + (size_t)bh * SQ * DH;

#pragma unroll
    for (int t = 0; t < 4; t++) {
        int idx = t * 1024 + tid * 4;
        *(float4*)&Qs[idx] = *(const float4*)&Qg[idx];
    }

    float m_i[4], l_i[4], acc[4][4];
#pragma unroll
    for (int ii = 0; ii < 4; ii++) {
        m_i[ii] = -INFINITY;
        l_i[ii] = 0.f;
#pragma unroll
        for (int dd = 0; dd < 4; dd++) acc[ii][dd] = 0.f;
    }

    for (int kt = 0; kt <= qt; kt++) {
        __syncthreads();
        const float* Kt = Kg + (size_t)kt * 64 * DH;
        const float* Vt = Vg + (size_t)kt * 64 * DH;
#pragma unroll
        for (int t = 0; t < 16; t++) {
            int idx = t * 256 + tid;
            int j = idx >> 6, d = idx & 63;
            KPs[j * 64 + ((d + j) & 63)] = Kt[idx];
        }
#pragma unroll
        for (int t = 0; t < 4; t++) {
            int idx = t * 1024 + tid * 4;
            *(float4*)&Vs[idx] = *(const float4*)&Vt[idx];
        }
        __syncthreads();

        float s[4][4];
#pragma unroll
        for (int ii = 0; ii < 4; ii++)
#pragma unroll
            for (int jj = 0; jj < 4; jj++) s[ii][jj] = 0.f;

#pragma unroll 4
        for (int d = 0; d < 64; d++) {
            float qv[4], kv[4];
#pragma unroll
            for (int ii = 0; ii < 4; ii++) qv[ii] = Qs[(ty * 4 + ii) * 64 + d];
#pragma unroll
            for (int jj = 0; jj < 4; jj++) {
                int j = tx * 4 + jj;
                kv[jj] = KPs[j * 64 + ((d + j) & 63)];
            }
#pragma unroll
            for (int ii = 0; ii < 4; ii++)
#pragma unroll
                for (int jj = 0; jj < 4; jj++)
                    s[ii][jj] = fmaf(qv[ii], kv[jj], s[ii][jj]);
        }

        bool diag = (kt == qt);
#pragma unroll
        for (int ii = 0; ii < 4; ii++) {
            int qi = qt * 64 + ty * 4 + ii;
#pragma unroll
            for (int jj = 0; jj < 4; jj++) {
                int kj = kt * 64 + tx * 4 + jj;
                float v = s[ii][jj] * 0.125f;
                if (diag && kj > qi) v = -1.25e8f;
                s[ii][jj] = v;
            }
        }

        float p[4][4];
#pragma unroll
        for (int ii = 0; ii < 4; ii++) {
            float rm = fmaxf(fmaxf(s[ii][0], s[ii][1]), fmaxf(s[ii][2], s[ii][3]));
            rm = fmaxf(rm, __shfl_xor_sync(0xffffffffu, rm, 1));
            rm = fmaxf(rm, __shfl_xor_sync(0xffffffffu, rm, 2));
            rm = fmaxf(rm, __shfl_xor_sync(0xffffffffu, rm, 4));
            rm = fmaxf(rm, __shfl_xor_sync(0xffffffffu, rm, 8));
            float mnew = fmaxf(m_i[ii], rm);
            float corr = __expf(m_i[ii] - mnew);
            float rs = 0.f;
#pragma unroll
            for (int jj = 0; jj < 4; jj++) {
                float pv = __expf(s[ii][jj] - mnew);
                p[ii][jj] = pv;
                rs += pv;
            }
            rs += __shfl_xor_sync(0xffffffffu, rs, 1);
            rs += __shfl_xor_sync(0xffffffffu, rs, 2);
            rs += __shfl_xor_sync(0xffffffffu, rs, 4);
            rs += __shfl_xor_sync(0xffffffffu, rs, 8);
            l_i[ii] = l_i[ii] * corr + rs;
            m_i[ii] = mnew;
#pragma unroll
            for (int dd = 0; dd < 4; dd++) acc[ii][dd] *= corr;
        }

        __syncthreads();
#pragma unroll
        for (int ii = 0; ii < 4; ii++)
#pragma unroll
            for (int jj = 0; jj < 4; jj++)
                KPs[(ty * 4 + ii) * 64 + tx * 4 + jj] = p[ii][jj];
        __syncthreads();

#pragma unroll 2
        for (int j = 0; j < 64; j++) {
            float4 v4 = *(const float4*)&Vs[j * 64 + tx * 4];
#pragma unroll
            for (int ii = 0; ii < 4; ii++) {
                float pv = KPs[(ty * 4 + ii) * 64 + j];
                acc[ii][0] = fmaf(pv, v4.x, acc[ii][0]);
                acc[ii][1] = fmaf(pv, v4.y, acc[ii][1]);
                acc[ii][2] = fmaf(pv, v4.z, acc[ii][2]);
                acc[ii][3] = fmaf(pv, v4.w, acc[ii][3]);
            }
        }
    }

    // finalize: split ctx into bf16 hi/lo for the output projection
    int b = bh >> 4, h = bh & 15;
#pragma unroll
    for (int ii = 0; ii < 4; ii++) {
        float inv = 1.0f / l_i[ii];
        int row = b * SQ + qt * 64 + ty * 4 + ii;
        size_t base = (size_t)row * DM + h * DH + tx * 4;
        union { __nv_bfloat16 h4[4]; uint2 u; } ph, pl;
#pragma unroll
        for (int q = 0; q < 4; q++) {
            float v = acc[ii][q] * inv;
            __nv_bfloat16 hi = __float2bfloat16(v);
            ph.h4[q] = hi;
            pl.h4[q] = __float2bfloat16(v - __bfloat162float(hi));
        }
        *(uint2*)&g_ch[base] = ph.u;
        *(uint2*)&g_cl[base] = pl.u;
    }
}

// ---------------------------------------------------------------------------
extern "C" void kernel_launch(void* const* d_in, const int* in_sizes, int n_in,
                              void* d_out, int out_size)
{
    const float* x  = (const float*)d_in[0];
    const float* Wq = (const float*)d_in[1];
    const float* bq = (const float*)d_in[2];
    const float* Wk = (const float*)d_in[3];
    const float* bk = (const float*)d_in[4];
    const float* Wv = (const float*)d_in[5];
    const float* bv = (const float*)d_in[6];
    const float* Wo = (const float*)d_in[7];
    const float* bo = (const float*)d_in[8];
    float* out = (float*)d_out;

    cudaFuncSetAttribute(gemm_tc, cudaFuncAttributeMaxDynamicSharedMemorySize, SMEM_DYN);

    convw_k<<<dim3(32, 32, 4), dim3(32, 8)>>>(Wq, Wk, Wv, Wo);
    convx_k<<<4096, 256>>>(x);
    gemm_tc<<<dim3(8, 32, 3), 256, SMEM_DYN>>>(bq, bk, bv, nullptr, 0);
    attn_k<<<dim3(32, 32), 256>>>();
    gemm_tc<<<dim3(8, 32, 1), 256, SMEM_DYN>>>(bo, bo, bo, out, 1);
}